// round 8
// baseline (speedup 1.0000x reference)
#include <cuda_runtime.h>
#include <math.h>
#include <stdint.h>

// Problem constants (fixed by the reference)
#define DM    1024
#define HH    16
#define DKH   64
#define BATCH 4
#define SEQ   2048
#define MTOT  (BATCH * SEQ)   // 8192

// ---------------------------------------------------------------------------
// Scratch (no allocations allowed -> __device__ globals)
// ---------------------------------------------------------------------------
__device__ __align__(128) float g_Q[(size_t)MTOT * DM];
__device__ __align__(128) float g_K[(size_t)MTOT * DM];
__device__ __align__(128) float g_V[(size_t)MTOT * DM];
__device__ __align__(128) float g_ctx[(size_t)MTOT * DM];
// tf32-preconverted copies of inputs (preserves R5 rounding semantics)
__device__ __align__(128) float c_q[(size_t)MTOT * DM];
__device__ __align__(128) float c_k[(size_t)MTOT * DM];
__device__ __align__(128) float c_v[(size_t)MTOT * DM];
__device__ __align__(128) float c_Wq[(size_t)DM * DM];
__device__ __align__(128) float c_Wk[(size_t)DM * DM];
__device__ __align__(128) float c_Wv[(size_t)DM * DM];
__device__ __align__(128) float c_Wo[(size_t)DM * DM];

// ---------------------------------------------------------------------------
// Helpers
// ---------------------------------------------------------------------------
__device__ __forceinline__ float f2tf32(float x) {
    uint32_t r;
    asm("cvt.rna.tf32.f32 %0, %1;" : "=r"(r) : "f"(x));
    return __uint_as_float(r);
}

__device__ __forceinline__ void mma_tf32(float (&d)[4],
                                         const uint32_t (&a)[4],
                                         const uint32_t (&b)[2]) {
    asm volatile(
        "mma.sync.aligned.m16n8k8.row.col.f32.tf32.tf32.f32 "
        "{%0,%1,%2,%3}, {%4,%5,%6,%7}, {%8,%9}, {%0,%1,%2,%3};"
        : "+f"(d[0]), "+f"(d[1]), "+f"(d[2]), "+f"(d[3])
        : "r"(a[0]), "r"(a[1]), "r"(a[2]), "r"(a[3]),
          "r"(b[0]), "r"(b[1]));
}

__device__ __forceinline__ void cp16(uint32_t dst_smem, const void* src) {
    asm volatile("cp.async.cg.shared.global [%0], [%1], 16;"
                 :: "r"(dst_smem), "l"(src));
}
__device__ __forceinline__ void cp_commit() {
    asm volatile("cp.async.commit_group;");
}
template <int N>
__device__ __forceinline__ void cp_wait() {
    asm volatile("cp.async.wait_group %0;" :: "n"(N));
}

// ---------------------------------------------------------------------------
// Elementwise tf32 pre-convert, 4 float4 per thread (MLP=4)
// ---------------------------------------------------------------------------
__global__ __launch_bounds__(256)
void conv_tf32_kernel(const float4* __restrict__ in, float4* __restrict__ out,
                      int n4)
{
    int base = blockIdx.x * 1024 + threadIdx.x;
#pragma unroll
    for (int j = 0; j < 4; j++) {
        int i = base + j * 256;
        if (i < n4) {
            float4 v = in[i];
            out[i] = make_float4(f2tf32(v.x), f2tf32(v.y), f2tf32(v.z), f2tf32(v.w));
        }
    }
}

// ---------------------------------------------------------------------------
// cp.async pipelined TF32 GEMM NT: C[M,N] = A[M,K] * B[N,K]^T
// Inputs MUST already be tf32-rounded. CTA tile 128x128, BK=32, 3 stages,
// ONE __syncthreads per stage (refill slot's readers finished last iter).
// 256 threads = 8 warps (2m x 4n), warp tile 64x32, m16n8k8 fragments.
// MODE epilogue: 0 = plain f32, 1 = tf32, 2 = tf32(0.125*x) (Q projection).
// ---------------------------------------------------------------------------
#define TBK 32
#define NST 3
#define NKB2 (DM / TBK)                   // 32
#define ARR_BYTES (128 * TBK * 4)         // 16KB per array per stage
#define STG_BYTES (2 * ARR_BYTES)         // 32KB
#define SMEM_G2 (NST * STG_BYTES)         // 96KB

template <int MODE>
__global__ __launch_bounds__(256)
void gemm_cp_kernel(const float* __restrict__ A,
                    const float* __restrict__ B,
                    float* __restrict__ C)
{
    extern __shared__ __align__(128) float smf[];
    const uint32_t smem_base = (uint32_t)__cvta_generic_to_shared(smf);

    const int tid = threadIdx.x;
    const int bn = blockIdx.x * 128;
    const int bm = blockIdx.y * 128;

    const int lane = tid & 31;
    const int wid  = tid >> 5;
    const int wm   = wid >> 2;          // 0..1
    const int wn   = wid & 3;           // 0..3
    const int g    = lane >> 2;         // 0..7
    const int tg   = lane & 3;          // 0..3

    float acc[4][4][4];
#pragma unroll
    for (int i = 0; i < 4; i++)
#pragma unroll
        for (int j = 0; j < 4; j++)
#pragma unroll
            for (int c = 0; c < 4; c++) acc[i][j][c] = 0.f;

    // ---- fill one stage: A/B, 128 rows x 8 units(16B) each, swizzled ----
    auto fill = [&](int slot, int kb) {
        const uint32_t ab = smem_base + slot * STG_BYTES;
        const uint32_t bb = ab + ARR_BYTES;
        const float* Ak = A + (size_t)bm * DM + kb * TBK;
        const float* Bk = B + (size_t)bn * DM + kb * TBK;
#pragma unroll
        for (int i = 0; i < 4; i++) {
            int idx = tid + i * 256;        // 0..1023
            int row = idx >> 3;             // 0..127
            int u   = idx & 7;              // 16B unit within 32-float row
            uint32_t off = row * 128 + ((u ^ (row & 7)) << 4);
            cp16(ab + off, Ak + (size_t)row * DM + u * 4);
            cp16(bb + off, Bk + (size_t)row * DM + u * 4);
        }
        cp_commit();
    };

    // swizzled float index for element (row, c) of a 128x32 block, c in [0,32)
    auto sidx = [&](int row, int c) -> int {
        return row * 32 + ((((c) >> 2) ^ (row & 7)) << 2) + (c & 3);
    };

    fill(0, 0);
    fill(1, 1);

    for (int s = 0; s < NKB2; s++) {
        const int slot = s % NST;
        if (s < NKB2 - 1) cp_wait<1>();
        else              cp_wait<0>();
        __syncthreads();

        // refill the slot read at iteration s-1 (fenced by the barrier above)
        if (s + 2 < NKB2) fill((s + 2) % NST, s + 2);

        const float* as = smf + (size_t)slot * (STG_BYTES / 4);
        const float* bs = as + ARR_BYTES / 4;

#pragma unroll
        for (int ks = 0; ks < 4; ks++) {
            uint32_t af[4][4];
            uint32_t bf[4][2];
            const int c0 = ks * 8 + tg;
#pragma unroll
            for (int mf = 0; mf < 4; mf++) {
                const int r0 = wm * 64 + mf * 16 + g;
                af[mf][0] = __float_as_uint(as[sidx(r0,     c0)]);
                af[mf][1] = __float_as_uint(as[sidx(r0 + 8, c0)]);
                af[mf][2] = __float_as_uint(as[sidx(r0,     c0 + 4)]);
                af[mf][3] = __float_as_uint(as[sidx(r0 + 8, c0 + 4)]);
            }
#pragma unroll
            for (int nf = 0; nf < 4; nf++) {
                const int r0 = wn * 32 + nf * 8 + g;
                bf[nf][0] = __float_as_uint(bs[sidx(r0, c0)]);
                bf[nf][1] = __float_as_uint(bs[sidx(r0, c0 + 4)]);
            }
#pragma unroll
            for (int mf = 0; mf < 4; mf++)
#pragma unroll
                for (int nf = 0; nf < 4; nf++)
                    mma_tf32(acc[mf][nf], af[mf], bf[nf]);
        }
    }

    auto ep = [&](float x) -> float {
        if (MODE == 0) return x;
        if (MODE == 1) return f2tf32(x);
        return f2tf32(x * 0.125f);
    };

#pragma unroll
    for (int mf = 0; mf < 4; mf++) {
#pragma unroll
        for (int nf = 0; nf < 4; nf++) {
            float* cp = C + (size_t)(bm + wm * 64 + mf * 16 + g) * DM
                          + bn + wn * 32 + nf * 8 + tg * 2;
            *(float2*)cp = make_float2(ep(acc[mf][nf][0]), ep(acc[mf][nf][1]));
            *(float2*)(cp + 8 * DM) = make_float2(ep(acc[mf][nf][2]), ep(acc[mf][nf][3]));
        }
    }
}

// ---------------------------------------------------------------------------
// Tensor-core flash attention v4: R5/R7 structure, but the exp-sum (l) is
// kept as PER-LANE partials (rescaled by alpha each tile) and reduced across
// the quad only in the epilogue — removes 16 serial SHFLs per kv tile from
// the softmax dependency chain.
// ---------------------------------------------------------------------------
#define KP 68
#define VP 72
#define QTILE 128
#define NKV   (SEQ / 64)   // 32 kv tiles

__global__ __launch_bounds__(128)
void attn_mma4_kernel(const float* __restrict__ Q,
                      const float* __restrict__ K,
                      const float* __restrict__ V,
                      float* __restrict__ ctx)
{
    const int bh = blockIdx.x;
    const int b  = bh / HH;
    const int h  = bh % HH;
    const int q0 = blockIdx.y * QTILE;

    extern __shared__ float sm[];
    float* Ks = sm;                         // [2][64*KP]
    float* Vs = Ks + 2 * 64 * KP;           // [2][64*VP]

    const int tid  = threadIdx.x;
    const int lane = tid & 31;
    const int warp = tid >> 5;
    const int wq   = warp * 32;
    const int g    = lane >> 2;
    const int tg   = lane & 3;
    const int idx_lo = (lane & ~3) | (tg >> 1);
    const int idx_hi = idx_lo + 2;
    const bool odd = (tg & 1);

    const float* Kbase = K + (size_t)b * SEQ * DM + h * DKH;
    const float* Vbase = V + (size_t)b * SEQ * DM + h * DKH;

    const uint32_t ks_smem = (uint32_t)__cvta_generic_to_shared(Ks);
    const uint32_t vs_smem = (uint32_t)__cvta_generic_to_shared(Vs);

    auto prefetch = [&](int t, int buf) {
#pragma unroll
        for (int i = 0; i < 8; i++) {
            int idx = tid + i * 128;
            int row = idx >> 4;
            int c4  = (idx & 15) * 4;
            const float* ks_src = Kbase + (size_t)(t * 64 + row) * DM + c4;
            const float* vs_src = Vbase + (size_t)(t * 64 + row) * DM + c4;
            cp16(ks_smem + (buf * 64 * KP + row * KP + c4) * 4, ks_src);
            cp16(vs_smem + (buf * 64 * VP + row * VP + c4) * 4, vs_src);
        }
        cp_commit();
    };

    uint32_t qa[2][8][4];
    {
        const float* Qb = Q + ((size_t)b * SEQ + q0 + wq) * DM + h * DKH;
#pragma unroll
        for (int mf = 0; mf < 2; mf++)
#pragma unroll
            for (int ks = 0; ks < 8; ks++) {
                const float* r0 = Qb + (size_t)(mf * 16 + g) * DM + ks * 8 + tg;
                const float* r1 = r0 + (size_t)8 * DM;
                qa[mf][ks][0] = __float_as_uint(r0[0]);
                qa[mf][ks][1] = __float_as_uint(r1[0]);
                qa[mf][ks][2] = __float_as_uint(r0[4]);
                qa[mf][ks][3] = __float_as_uint(r1[4]);
            }
    }

    prefetch(0, 0);

    float m_r[2][2], l_r[2][2];     // l_r = per-lane partial sums
    float Oacc[2][8][4];
#pragma unroll
    for (int mf = 0; mf < 2; mf++) {
        m_r[mf][0] = -INFINITY; m_r[mf][1] = -INFINITY;
        l_r[mf][0] = 0.f;       l_r[mf][1] = 0.f;
#pragma unroll
        for (int nf = 0; nf < 8; nf++)
#pragma unroll
            for (int c = 0; c < 4; c++) Oacc[mf][nf][c] = 0.f;
    }

    int buf = 0;
    for (int t = 0; t < NKV; t++) {
        if (t + 1 < NKV) prefetch(t + 1, buf ^ 1);
        else             cp_commit();
        cp_wait<1>();
        __syncthreads();

        const float* kt = Ks + buf * 64 * KP;
        const float* vt = Vs + buf * 64 * VP;

#pragma unroll
        for (int kc = 0; kc < 2; kc++) {
            float sacc[2][4][4];
#pragma unroll
            for (int mf = 0; mf < 2; mf++)
#pragma unroll
                for (int nf = 0; nf < 4; nf++)
#pragma unroll
                    for (int c = 0; c < 4; c++) sacc[mf][nf][c] = 0.f;

#pragma unroll
            for (int ks = 0; ks < 8; ks++) {
#pragma unroll
                for (int nf = 0; nf < 4; nf++) {
                    const float* p = &kt[(kc * 32 + nf * 8 + g) * KP + ks * 8 + tg];
                    uint32_t bf[2] = {__float_as_uint(p[0]), __float_as_uint(p[4])};
                    mma_tf32(sacc[0][nf], qa[0][ks], bf);
                    mma_tf32(sacc[1][nf], qa[1][ks], bf);
                }
            }

#pragma unroll
            for (int mf = 0; mf < 2; mf++) {
                float mx0 = -INFINITY, mx1 = -INFINITY;
#pragma unroll
                for (int nf = 0; nf < 4; nf++) {
                    mx0 = fmaxf(mx0, fmaxf(sacc[mf][nf][0], sacc[mf][nf][1]));
                    mx1 = fmaxf(mx1, fmaxf(sacc[mf][nf][2], sacc[mf][nf][3]));
                }
                mx0 = fmaxf(mx0, __shfl_xor_sync(0xffffffffu, mx0, 1));
                mx0 = fmaxf(mx0, __shfl_xor_sync(0xffffffffu, mx0, 2));
                mx1 = fmaxf(mx1, __shfl_xor_sync(0xffffffffu, mx1, 1));
                mx1 = fmaxf(mx1, __shfl_xor_sync(0xffffffffu, mx1, 2));

                const float mn0 = fmaxf(m_r[mf][0], mx0);
                const float mn1 = fmaxf(m_r[mf][1], mx1);
                const float al0 = __expf(m_r[mf][0] - mn0);
                const float al1 = __expf(m_r[mf][1] - mn1);

                float s0 = 0.f, s1 = 0.f;
#pragma unroll
                for (int nf = 0; nf < 4; nf++) {
                    float p0 = __expf(sacc[mf][nf][0] - mn0);
                    float p1 = __expf(sacc[mf][nf][1] - mn0);
                    float p2 = __expf(sacc[mf][nf][2] - mn1);
                    float p3 = __expf(sacc[mf][nf][3] - mn1);
                    sacc[mf][nf][0] = p0; sacc[mf][nf][1] = p1;
                    sacc[mf][nf][2] = p2; sacc[mf][nf][3] = p3;
                    s0 += p0 + p1;
                    s1 += p2 + p3;
                }
                // per-lane partials: NO shfl reduction here
                m_r[mf][0] = mn0; m_r[mf][1] = mn1;
                l_r[mf][0] = l_r[mf][0] * al0 + s0;
                l_r[mf][1] = l_r[mf][1] * al1 + s1;

#pragma unroll
                for (int nf = 0; nf < 8; nf++) {
                    Oacc[mf][nf][0] *= al0; Oacc[mf][nf][1] *= al0;
                    Oacc[mf][nf][2] *= al1; Oacc[mf][nf][3] *= al1;
                }
            }

            uint32_t af[2][4][4];
#pragma unroll
            for (int mf = 0; mf < 2; mf++)
#pragma unroll
                for (int nf = 0; nf < 4; nf++) {
                    float v0l = __shfl_sync(0xffffffffu, sacc[mf][nf][0], idx_lo);
                    float v1l = __shfl_sync(0xffffffffu, sacc[mf][nf][1], idx_lo);
                    float v2l = __shfl_sync(0xffffffffu, sacc[mf][nf][2], idx_lo);
                    float v3l = __shfl_sync(0xffffffffu, sacc[mf][nf][3], idx_lo);
                    float v0h = __shfl_sync(0xffffffffu, sacc[mf][nf][0], idx_hi);
                    float v1h = __shfl_sync(0xffffffffu, sacc[mf][nf][1], idx_hi);
                    float v2h = __shfl_sync(0xffffffffu, sacc[mf][nf][2], idx_hi);
                    float v3h = __shfl_sync(0xffffffffu, sacc[mf][nf][3], idx_hi);
                    af[mf][nf][0] = __float_as_uint(f2tf32(odd ? v1l : v0l));
                    af[mf][nf][1] = __float_as_uint(f2tf32(odd ? v3l : v2l));
                    af[mf][nf][2] = __float_as_uint(f2tf32(odd ? v1h : v0h));
                    af[mf][nf][3] = __float_as_uint(f2tf32(odd ? v3h : v2h));
                }

#pragma unroll
            for (int ksl = 0; ksl < 4; ksl++) {
#pragma unroll
                for (int nf = 0; nf < 8; nf++) {
                    uint32_t bf[2] = {
                        __float_as_uint(vt[(kc * 32 + ksl * 8 + tg) * VP + nf * 8 + g]),
                        __float_as_uint(vt[(kc * 32 + ksl * 8 + tg + 4) * VP + nf * 8 + g])
                    };
                    mma_tf32(Oacc[0][nf], af[0][ksl], bf);
                    mma_tf32(Oacc[1][nf], af[1][ksl], bf);
                }
            }
        }

        __syncthreads();
        buf ^= 1;
    }

    // epilogue: reduce l across the quad, then tf32-rounded ctx store
#pragma unroll
    for (int mf = 0; mf < 2; mf++) {
        float l0 = l_r[mf][0], l1 = l_r[mf][1];
        l0 += __shfl_xor_sync(0xffffffffu, l0, 1);
        l0 += __shfl_xor_sync(0xffffffffu, l0, 2);
        l1 += __shfl_xor_sync(0xffffffffu, l1, 1);
        l1 += __shfl_xor_sync(0xffffffffu, l1, 2);
        const float inv0 = 1.f / l0;
        const float inv1 = 1.f / l1;
        float* out = ctx + ((size_t)b * SEQ + q0 + wq + mf * 16) * DM + h * DKH;
#pragma unroll
        for (int nf = 0; nf < 8; nf++) {
            *(float2*)&out[(size_t)g * DM + nf * 8 + tg * 2] =
                make_float2(f2tf32(Oacc[mf][nf][0] * inv0), f2tf32(Oacc[mf][nf][1] * inv0));
            *(float2*)&out[(size_t)(g + 8) * DM + nf * 8 + tg * 2] =
                make_float2(f2tf32(Oacc[mf][nf][2] * inv1), f2tf32(Oacc[mf][nf][3] * inv1));
        }
    }
}

// ---------------------------------------------------------------------------
// Launch
// ---------------------------------------------------------------------------
extern "C" void kernel_launch(void* const* d_in, const int* in_sizes, int n_in,
                              void* d_out, int out_size)
{
    (void)in_sizes; (void)n_in; (void)out_size;
    const float* q  = (const float*)d_in[0];
    const float* k  = (const float*)d_in[1];
    const float* v  = (const float*)d_in[2];
    const float* Wq = (const float*)d_in[3];
    const float* Wk = (const float*)d_in[4];
    const float* Wv = (const float*)d_in[5];
    const float* Wo = (const float*)d_in[6];
    float* out = (float*)d_out;

    float *gQ, *gK, *gV, *gC;
    float *cq, *ck, *cv, *cWq, *cWk, *cWv, *cWo;
    cudaGetSymbolAddress((void**)&gQ, g_Q);
    cudaGetSymbolAddress((void**)&gK, g_K);
    cudaGetSymbolAddress((void**)&gV, g_V);
    cudaGetSymbolAddress((void**)&gC, g_ctx);
    cudaGetSymbolAddress((void**)&cq, c_q);
    cudaGetSymbolAddress((void**)&ck, c_k);
    cudaGetSymbolAddress((void**)&cv, c_v);
    cudaGetSymbolAddress((void**)&cWq, c_Wq);
    cudaGetSymbolAddress((void**)&cWk, c_Wk);
    cudaGetSymbolAddress((void**)&cWv, c_Wv);
    cudaGetSymbolAddress((void**)&cWo, c_Wo);

    const int attn_smem = (2 * 64 * KP + 2 * 64 * VP) * (int)sizeof(float); // 71680
    static bool attr_set = false;
    if (!attr_set) {
        cudaFuncSetAttribute(attn_mma4_kernel,
                             cudaFuncAttributeMaxDynamicSharedMemorySize, attn_smem);
        cudaFuncSetAttribute(gemm_cp_kernel<0>,
                             cudaFuncAttributeMaxDynamicSharedMemorySize, SMEM_G2);
        cudaFuncSetAttribute(gemm_cp_kernel<1>,
                             cudaFuncAttributeMaxDynamicSharedMemorySize, SMEM_G2);
        cudaFuncSetAttribute(gemm_cp_kernel<2>,
                             cudaFuncAttributeMaxDynamicSharedMemorySize, SMEM_G2);
        attr_set = true;
    }

    // ---- pre-convert inputs to tf32 (preserves R5 rounding points) ----
    const int n4_x = MTOT * DM / 4;   // 2M float4
    const int n4_w = DM * DM / 4;     // 256K float4
    conv_tf32_kernel<<<(n4_x + 1023) / 1024, 256>>>((const float4*)q,  (float4*)cq,  n4_x);
    conv_tf32_kernel<<<(n4_x + 1023) / 1024, 256>>>((const float4*)k,  (float4*)ck,  n4_x);
    conv_tf32_kernel<<<(n4_x + 1023) / 1024, 256>>>((const float4*)v,  (float4*)cv,  n4_x);
    conv_tf32_kernel<<<(n4_w + 1023) / 1024, 256>>>((const float4*)Wq, (float4*)cWq, n4_w);
    conv_tf32_kernel<<<(n4_w + 1023) / 1024, 256>>>((const float4*)Wk, (float4*)cWk, n4_w);
    conv_tf32_kernel<<<(n4_w + 1023) / 1024, 256>>>((const float4*)Wv, (float4*)cWv, n4_w);
    conv_tf32_kernel<<<(n4_w + 1023) / 1024, 256>>>((const float4*)Wo, (float4*)cWo, n4_w);

    dim3 ggrid(DM / 128, MTOT / 128);   // (8, 64)
    gemm_cp_kernel<2><<<ggrid, 256, SMEM_G2>>>(cq, cWq, gQ);  // Q: tf32 + scale
    gemm_cp_kernel<1><<<ggrid, 256, SMEM_G2>>>(ck, cWk, gK);  // K: tf32
    gemm_cp_kernel<1><<<ggrid, 256, SMEM_G2>>>(cv, cWv, gV);  // V: tf32

    dim3 agrid(BATCH * HH, SEQ / QTILE);   // (64, 16)
    attn_mma4_kernel<<<agrid, 128, attn_smem>>>(gQ, gK, gV, gC);

    gemm_cp_kernel<0><<<ggrid, 256, SMEM_G2>>>(gC, cWo, out); // plain f32 out
}

// round 9
// speedup vs baseline: 1.0501x; 1.0501x over previous
#include <cuda_runtime.h>
#include <math.h>
#include <stdint.h>

// Problem constants (fixed by the reference)
#define DM    1024
#define HH    16
#define DKH   64
#define BATCH 4
#define SEQ   2048
#define MTOT  (BATCH * SEQ)   // 8192

// ---------------------------------------------------------------------------
// Scratch (no allocations allowed -> __device__ globals)
// ---------------------------------------------------------------------------
__device__ __align__(128) float g_Q[(size_t)MTOT * DM];
__device__ __align__(128) float g_K[(size_t)MTOT * DM];
__device__ __align__(128) float g_V[(size_t)MTOT * DM];
__device__ __align__(128) float g_ctx[(size_t)MTOT * DM];
// tf32-preconverted copies of inputs (preserves R5 rounding semantics)
__device__ __align__(128) float c_q[(size_t)MTOT * DM];
__device__ __align__(128) float c_k[(size_t)MTOT * DM];
__device__ __align__(128) float c_v[(size_t)MTOT * DM];
__device__ __align__(128) float c_Wq[(size_t)DM * DM];
__device__ __align__(128) float c_Wk[(size_t)DM * DM];
__device__ __align__(128) float c_Wv[(size_t)DM * DM];
__device__ __align__(128) float c_Wo[(size_t)DM * DM];

// ---------------------------------------------------------------------------
// Helpers
// ---------------------------------------------------------------------------
__device__ __forceinline__ float f2tf32(float x) {
    uint32_t r;
    asm("cvt.rna.tf32.f32 %0, %1;" : "=r"(r) : "f"(x));
    return __uint_as_float(r);
}

__device__ __forceinline__ void mma_tf32(float (&d)[4],
                                         const uint32_t (&a)[4],
                                         const uint32_t (&b)[2]) {
    asm volatile(
        "mma.sync.aligned.m16n8k8.row.col.f32.tf32.tf32.f32 "
        "{%0,%1,%2,%3}, {%4,%5,%6,%7}, {%8,%9}, {%0,%1,%2,%3};"
        : "+f"(d[0]), "+f"(d[1]), "+f"(d[2]), "+f"(d[3])
        : "r"(a[0]), "r"(a[1]), "r"(a[2]), "r"(a[3]),
          "r"(b[0]), "r"(b[1]));
}

__device__ __forceinline__ void cp16(uint32_t dst_smem, const void* src) {
    asm volatile("cp.async.cg.shared.global [%0], [%1], 16;"
                 :: "r"(dst_smem), "l"(src));
}
__device__ __forceinline__ void cp_commit() {
    asm volatile("cp.async.commit_group;");
}
template <int N>
__device__ __forceinline__ void cp_wait() {
    asm volatile("cp.async.wait_group %0;" :: "n"(N));
}

// ---------------------------------------------------------------------------
// Fused elementwise tf32 pre-convert: one launch converts all 7 tensors.
// grid.y selects the tensor; oversized grid.x blocks exit early.
// ---------------------------------------------------------------------------
struct ConvArgs {
    const float4* src[7];
    float4*       dst[7];
    int           n4[7];
};

__global__ __launch_bounds__(256)
void conv_all_kernel(ConvArgs a)
{
    const int seg = blockIdx.y;
    const float4* __restrict__ in = a.src[seg];
    float4* __restrict__ out = a.dst[seg];
    const int n4 = a.n4[seg];
    int base = blockIdx.x * 1024 + threadIdx.x;
    if (base >= n4) return;
#pragma unroll
    for (int j = 0; j < 4; j++) {
        int i = base + j * 256;
        if (i < n4) {
            float4 v = in[i];
            out[i] = make_float4(f2tf32(v.x), f2tf32(v.y), f2tf32(v.z), f2tf32(v.w));
        }
    }
}

// ---------------------------------------------------------------------------
// cp.async pipelined TF32 GEMM NT: C[M,N] = A[M,K] * B[N,K]^T
// Inputs MUST already be tf32-rounded. CTA tile 128x128, BK=64, 3 stages,
// ONE __syncthreads per iteration: the refill target is the slot read LAST
// iteration, fenced by the top-of-loop barrier. 16 barriers total, 128 MMAs
// of cover each; every cp.async group gets a full iteration to land.
// 256 threads = 8 warps (2m x 4n), warp tile 64x32, m16n8k8 fragments.
// MODE epilogue: 0 = plain f32, 1 = tf32, 2 = tf32(0.125*x) (Q projection).
// ---------------------------------------------------------------------------
#define TBK 64
#define NST 3
#define NKB2 (DM / TBK)                  // 16
#define ARR_BYTES (128 * TBK * 4)        // 32KB: two 16KB col-blocks
#define STG_BYTES (2 * ARR_BYTES)        // A + B = 64KB
#define SMEM_G2 (NST * STG_BYTES)        // 192KB

template <int MODE>
__global__ __launch_bounds__(256)
void gemm_cp_kernel(const float* __restrict__ A,
                    const float* __restrict__ B,
                    float* __restrict__ C)
{
    extern __shared__ __align__(128) float smf[];
    const uint32_t smem_base = (uint32_t)__cvta_generic_to_shared(smf);

    const int tid = threadIdx.x;
    const int bn = blockIdx.x * 128;
    const int bm = blockIdx.y * 128;

    const int lane = tid & 31;
    const int wid  = tid >> 5;
    const int wm   = wid >> 2;          // 0..1
    const int wn   = wid & 3;           // 0..3
    const int g    = lane >> 2;         // 0..7
    const int tg   = lane & 3;          // 0..3

    float acc[4][4][4];
#pragma unroll
    for (int i = 0; i < 4; i++)
#pragma unroll
        for (int j = 0; j < 4; j++)
#pragma unroll
            for (int c = 0; c < 4; c++) acc[i][j][c] = 0.f;

    // ---- fill one stage: A/B, 128 rows x 16 units(16B) each, swizzled ----
    auto fill = [&](int slot, int kb) {
        const uint32_t ab = smem_base + slot * STG_BYTES;
        const uint32_t bb = ab + ARR_BYTES;
        const float* Ak = A + (size_t)bm * DM + kb * TBK;
        const float* Bk = B + (size_t)bn * DM + kb * TBK;
#pragma unroll
        for (int i = 0; i < 8; i++) {
            int idx = tid + i * 256;        // 0..2047
            int row = idx >> 4;             // 0..127
            int u   = idx & 15;             // 16B unit within 64-float row
            uint32_t off = (u >> 3) * 16384 + row * 128
                         + (((u & 7) ^ (row & 7)) << 4);
            cp16(ab + off, Ak + (size_t)row * DM + u * 4);
            cp16(bb + off, Bk + (size_t)row * DM + u * 4);
        }
        cp_commit();
    };

    // swizzled float index for element (row, c) of a 128x64 block, c in [0,64)
    auto sidx = [&](int row, int c) -> int {
        return (c >> 5) * 4096 + row * 32
             + ((((c & 31) >> 2) ^ (row & 7)) << 2) + (c & 3);
    };

    fill(0, 0);
    fill(1, 1);

    for (int s = 0; s < NKB2; s++) {
        const int slot = s % NST;
        if (s < NKB2 - 1) cp_wait<1>();
        else              cp_wait<0>();
        __syncthreads();

        // refill the slot read at iteration s-1 (fenced by the barrier above)
        if (s + 2 < NKB2) fill((s + 2) % NST, s + 2);

        const float* as = smf + (size_t)slot * (STG_BYTES / 4);
        const float* bs = as + ARR_BYTES / 4;

#pragma unroll
        for (int ks = 0; ks < 8; ks++) {
            uint32_t af[4][4];
            uint32_t bf[4][2];
            const int c0 = ks * 8 + tg;
#pragma unroll
            for (int mf = 0; mf < 4; mf++) {
                const int r0 = wm * 64 + mf * 16 + g;
                af[mf][0] = __float_as_uint(as[sidx(r0,     c0)]);
                af[mf][1] = __float_as_uint(as[sidx(r0 + 8, c0)]);
                af[mf][2] = __float_as_uint(as[sidx(r0,     c0 + 4)]);
                af[mf][3] = __float_as_uint(as[sidx(r0 + 8, c0 + 4)]);
            }
#pragma unroll
            for (int nf = 0; nf < 4; nf++) {
                const int r0 = wn * 32 + nf * 8 + g;
                bf[nf][0] = __float_as_uint(bs[sidx(r0, c0)]);
                bf[nf][1] = __float_as_uint(bs[sidx(r0, c0 + 4)]);
            }
#pragma unroll
            for (int mf = 0; mf < 4; mf++)
#pragma unroll
                for (int nf = 0; nf < 4; nf++)
                    mma_tf32(acc[mf][nf], af[mf], bf[nf]);
        }
    }

    auto ep = [&](float x) -> float {
        if (MODE == 0) return x;
        if (MODE == 1) return f2tf32(x);
        return f2tf32(x * 0.125f);
    };

#pragma unroll
    for (int mf = 0; mf < 4; mf++) {
#pragma unroll
        for (int nf = 0; nf < 4; nf++) {
            float* cp = C + (size_t)(bm + wm * 64 + mf * 16 + g) * DM
                          + bn + wn * 32 + nf * 8 + tg * 2;
            *(float2*)cp = make_float2(ep(acc[mf][nf][0]), ep(acc[mf][nf][1]));
            *(float2*)(cp + 8 * DM) = make_float2(ep(acc[mf][nf][2]), ep(acc[mf][nf][3]));
        }
    }
}

// ---------------------------------------------------------------------------
// Tensor-core flash attention v4 (R8, verified): per-lane l partials,
// reduced across the quad only in the epilogue.
// ---------------------------------------------------------------------------
#define KP 68
#define VP 72
#define QTILE 128
#define NKV   (SEQ / 64)   // 32 kv tiles

__global__ __launch_bounds__(128)
void attn_mma4_kernel(const float* __restrict__ Q,
                      const float* __restrict__ K,
                      const float* __restrict__ V,
                      float* __restrict__ ctx)
{
    const int bh = blockIdx.x;
    const int b  = bh / HH;
    const int h  = bh % HH;
    const int q0 = blockIdx.y * QTILE;

    extern __shared__ float sm[];
    float* Ks = sm;                         // [2][64*KP]
    float* Vs = Ks + 2 * 64 * KP;           // [2][64*VP]

    const int tid  = threadIdx.x;
    const int lane = tid & 31;
    const int warp = tid >> 5;
    const int wq   = warp * 32;
    const int g    = lane >> 2;
    const int tg   = lane & 3;
    const int idx_lo = (lane & ~3) | (tg >> 1);
    const int idx_hi = idx_lo + 2;
    const bool odd = (tg & 1);

    const float* Kbase = K + (size_t)b * SEQ * DM + h * DKH;
    const float* Vbase = V + (size_t)b * SEQ * DM + h * DKH;

    const uint32_t ks_smem = (uint32_t)__cvta_generic_to_shared(Ks);
    const uint32_t vs_smem = (uint32_t)__cvta_generic_to_shared(Vs);

    auto prefetch = [&](int t, int buf) {
#pragma unroll
        for (int i = 0; i < 8; i++) {
            int idx = tid + i * 128;
            int row = idx >> 4;
            int c4  = (idx & 15) * 4;
            const float* ks_src = Kbase + (size_t)(t * 64 + row) * DM + c4;
            const float* vs_src = Vbase + (size_t)(t * 64 + row) * DM + c4;
            cp16(ks_smem + (buf * 64 * KP + row * KP + c4) * 4, ks_src);
            cp16(vs_smem + (buf * 64 * VP + row * VP + c4) * 4, vs_src);
        }
        cp_commit();
    };

    uint32_t qa[2][8][4];
    {
        const float* Qb = Q + ((size_t)b * SEQ + q0 + wq) * DM + h * DKH;
#pragma unroll
        for (int mf = 0; mf < 2; mf++)
#pragma unroll
            for (int ks = 0; ks < 8; ks++) {
                const float* r0 = Qb + (size_t)(mf * 16 + g) * DM + ks * 8 + tg;
                const float* r1 = r0 + (size_t)8 * DM;
                qa[mf][ks][0] = __float_as_uint(r0[0]);
                qa[mf][ks][1] = __float_as_uint(r1[0]);
                qa[mf][ks][2] = __float_as_uint(r0[4]);
                qa[mf][ks][3] = __float_as_uint(r1[4]);
            }
    }

    prefetch(0, 0);

    float m_r[2][2], l_r[2][2];     // l_r = per-lane partial sums
    float Oacc[2][8][4];
#pragma unroll
    for (int mf = 0; mf < 2; mf++) {
        m_r[mf][0] = -INFINITY; m_r[mf][1] = -INFINITY;
        l_r[mf][0] = 0.f;       l_r[mf][1] = 0.f;
#pragma unroll
        for (int nf = 0; nf < 8; nf++)
#pragma unroll
            for (int c = 0; c < 4; c++) Oacc[mf][nf][c] = 0.f;
    }

    int buf = 0;
    for (int t = 0; t < NKV; t++) {
        if (t + 1 < NKV) prefetch(t + 1, buf ^ 1);
        else             cp_commit();
        cp_wait<1>();
        __syncthreads();

        const float* kt = Ks + buf * 64 * KP;
        const float* vt = Vs + buf * 64 * VP;

#pragma unroll
        for (int kc = 0; kc < 2; kc++) {
            float sacc[2][4][4];
#pragma unroll
            for (int mf = 0; mf < 2; mf++)
#pragma unroll
                for (int nf = 0; nf < 4; nf++)
#pragma unroll
                    for (int c = 0; c < 4; c++) sacc[mf][nf][c] = 0.f;

#pragma unroll
            for (int ks = 0; ks < 8; ks++) {
#pragma unroll
                for (int nf = 0; nf < 4; nf++) {
                    const float* p = &kt[(kc * 32 + nf * 8 + g) * KP + ks * 8 + tg];
                    uint32_t bf[2] = {__float_as_uint(p[0]), __float_as_uint(p[4])};
                    mma_tf32(sacc[0][nf], qa[0][ks], bf);
                    mma_tf32(sacc[1][nf], qa[1][ks], bf);
                }
            }

#pragma unroll
            for (int mf = 0; mf < 2; mf++) {
                float mx0 = -INFINITY, mx1 = -INFINITY;
#pragma unroll
                for (int nf = 0; nf < 4; nf++) {
                    mx0 = fmaxf(mx0, fmaxf(sacc[mf][nf][0], sacc[mf][nf][1]));
                    mx1 = fmaxf(mx1, fmaxf(sacc[mf][nf][2], sacc[mf][nf][3]));
                }
                mx0 = fmaxf(mx0, __shfl_xor_sync(0xffffffffu, mx0, 1));
                mx0 = fmaxf(mx0, __shfl_xor_sync(0xffffffffu, mx0, 2));
                mx1 = fmaxf(mx1, __shfl_xor_sync(0xffffffffu, mx1, 1));
                mx1 = fmaxf(mx1, __shfl_xor_sync(0xffffffffu, mx1, 2));

                const float mn0 = fmaxf(m_r[mf][0], mx0);
                const float mn1 = fmaxf(m_r[mf][1], mx1);
                const float al0 = __expf(m_r[mf][0] - mn0);
                const float al1 = __expf(m_r[mf][1] - mn1);

                float s0 = 0.f, s1 = 0.f;
#pragma unroll
                for (int nf = 0; nf < 4; nf++) {
                    float p0 = __expf(sacc[mf][nf][0] - mn0);
                    float p1 = __expf(sacc[mf][nf][1] - mn0);
                    float p2 = __expf(sacc[mf][nf][2] - mn1);
                    float p3 = __expf(sacc[mf][nf][3] - mn1);
                    sacc[mf][nf][0] = p0; sacc[mf][nf][1] = p1;
                    sacc[mf][nf][2] = p2; sacc[mf][nf][3] = p3;
                    s0 += p0 + p1;
                    s1 += p2 + p3;
                }
                // per-lane partials: NO shfl reduction here
                m_r[mf][0] = mn0; m_r[mf][1] = mn1;
                l_r[mf][0] = l_r[mf][0] * al0 + s0;
                l_r[mf][1] = l_r[mf][1] * al1 + s1;

#pragma unroll
                for (int nf = 0; nf < 8; nf++) {
                    Oacc[mf][nf][0] *= al0; Oacc[mf][nf][1] *= al0;
                    Oacc[mf][nf][2] *= al1; Oacc[mf][nf][3] *= al1;
                }
            }

            uint32_t af[2][4][4];
#pragma unroll
            for (int mf = 0; mf < 2; mf++)
#pragma unroll
                for (int nf = 0; nf < 4; nf++) {
                    float v0l = __shfl_sync(0xffffffffu, sacc[mf][nf][0], idx_lo);
                    float v1l = __shfl_sync(0xffffffffu, sacc[mf][nf][1], idx_lo);
                    float v2l = __shfl_sync(0xffffffffu, sacc[mf][nf][2], idx_lo);
                    float v3l = __shfl_sync(0xffffffffu, sacc[mf][nf][3], idx_lo);
                    float v0h = __shfl_sync(0xffffffffu, sacc[mf][nf][0], idx_hi);
                    float v1h = __shfl_sync(0xffffffffu, sacc[mf][nf][1], idx_hi);
                    float v2h = __shfl_sync(0xffffffffu, sacc[mf][nf][2], idx_hi);
                    float v3h = __shfl_sync(0xffffffffu, sacc[mf][nf][3], idx_hi);
                    af[mf][nf][0] = __float_as_uint(f2tf32(odd ? v1l : v0l));
                    af[mf][nf][1] = __float_as_uint(f2tf32(odd ? v3l : v2l));
                    af[mf][nf][2] = __float_as_uint(f2tf32(odd ? v1h : v0h));
                    af[mf][nf][3] = __float_as_uint(f2tf32(odd ? v3h : v2h));
                }

#pragma unroll
            for (int ksl = 0; ksl < 4; ksl++) {
#pragma unroll
                for (int nf = 0; nf < 8; nf++) {
                    uint32_t bf[2] = {
                        __float_as_uint(vt[(kc * 32 + ksl * 8 + tg) * VP + nf * 8 + g]),
                        __float_as_uint(vt[(kc * 32 + ksl * 8 + tg + 4) * VP + nf * 8 + g])
                    };
                    mma_tf32(Oacc[0][nf], af[0][ksl], bf);
                    mma_tf32(Oacc[1][nf], af[1][ksl], bf);
                }
            }
        }

        __syncthreads();
        buf ^= 1;
    }

    // epilogue: reduce l across the quad, then tf32-rounded ctx store
#pragma unroll
    for (int mf = 0; mf < 2; mf++) {
        float l0 = l_r[mf][0], l1 = l_r[mf][1];
        l0 += __shfl_xor_sync(0xffffffffu, l0, 1);
        l0 += __shfl_xor_sync(0xffffffffu, l0, 2);
        l1 += __shfl_xor_sync(0xffffffffu, l1, 1);
        l1 += __shfl_xor_sync(0xffffffffu, l1, 2);
        const float inv0 = 1.f / l0;
        const float inv1 = 1.f / l1;
        float* out = ctx + ((size_t)b * SEQ + q0 + wq + mf * 16) * DM + h * DKH;
#pragma unroll
        for (int nf = 0; nf < 8; nf++) {
            *(float2*)&out[(size_t)g * DM + nf * 8 + tg * 2] =
                make_float2(f2tf32(Oacc[mf][nf][0] * inv0), f2tf32(Oacc[mf][nf][1] * inv0));
            *(float2*)&out[(size_t)(g + 8) * DM + nf * 8 + tg * 2] =
                make_float2(f2tf32(Oacc[mf][nf][2] * inv1), f2tf32(Oacc[mf][nf][3] * inv1));
        }
    }
}

// ---------------------------------------------------------------------------
// Launch
// ---------------------------------------------------------------------------
extern "C" void kernel_launch(void* const* d_in, const int* in_sizes, int n_in,
                              void* d_out, int out_size)
{
    (void)in_sizes; (void)n_in; (void)out_size;
    const float* q  = (const float*)d_in[0];
    const float* k  = (const float*)d_in[1];
    const float* v  = (const float*)d_in[2];
    const float* Wq = (const float*)d_in[3];
    const float* Wk = (const float*)d_in[4];
    const float* Wv = (const float*)d_in[5];
    const float* Wo = (const float*)d_in[6];
    float* out = (float*)d_out;

    float *gQ, *gK, *gV, *gC;
    float *cq, *ck, *cv, *cWq, *cWk, *cWv, *cWo;
    cudaGetSymbolAddress((void**)&gQ, g_Q);
    cudaGetSymbolAddress((void**)&gK, g_K);
    cudaGetSymbolAddress((void**)&gV, g_V);
    cudaGetSymbolAddress((void**)&gC, g_ctx);
    cudaGetSymbolAddress((void**)&cq, c_q);
    cudaGetSymbolAddress((void**)&ck, c_k);
    cudaGetSymbolAddress((void**)&cv, c_v);
    cudaGetSymbolAddress((void**)&cWq, c_Wq);
    cudaGetSymbolAddress((void**)&cWk, c_Wk);
    cudaGetSymbolAddress((void**)&cWv, c_Wv);
    cudaGetSymbolAddress((void**)&cWo, c_Wo);

    const int attn_smem = (2 * 64 * KP + 2 * 64 * VP) * (int)sizeof(float); // 71680
    static bool attr_set = false;
    if (!attr_set) {
        cudaFuncSetAttribute(attn_mma4_kernel,
                             cudaFuncAttributeMaxDynamicSharedMemorySize, attn_smem);
        cudaFuncSetAttribute(gemm_cp_kernel<0>,
                             cudaFuncAttributeMaxDynamicSharedMemorySize, SMEM_G2);
        cudaFuncSetAttribute(gemm_cp_kernel<1>,
                             cudaFuncAttributeMaxDynamicSharedMemorySize, SMEM_G2);
        cudaFuncSetAttribute(gemm_cp_kernel<2>,
                             cudaFuncAttributeMaxDynamicSharedMemorySize, SMEM_G2);
        attr_set = true;
    }

    // ---- fused tf32 pre-convert: one launch for all 7 tensors ----
    const int n4_x = MTOT * DM / 4;   // 2M float4
    const int n4_w = DM * DM / 4;     // 256K float4
    ConvArgs ca;
    ca.src[0] = (const float4*)q;  ca.dst[0] = (float4*)cq;  ca.n4[0] = n4_x;
    ca.src[1] = (const float4*)k;  ca.dst[1] = (float4*)ck;  ca.n4[1] = n4_x;
    ca.src[2] = (const float4*)v;  ca.dst[2] = (float4*)cv;  ca.n4[2] = n4_x;
    ca.src[3] = (const float4*)Wq; ca.dst[3] = (float4*)cWq; ca.n4[3] = n4_w;
    ca.src[4] = (const float4*)Wk; ca.dst[4] = (float4*)cWk; ca.n4[4] = n4_w;
    ca.src[5] = (const float4*)Wv; ca.dst[5] = (float4*)cWv; ca.n4[5] = n4_w;
    ca.src[6] = (const float4*)Wo; ca.dst[6] = (float4*)cWo; ca.n4[6] = n4_w;
    dim3 cgrid((n4_x + 1023) / 1024, 7);
    conv_all_kernel<<<cgrid, 256>>>(ca);

    dim3 ggrid(DM / 128, MTOT / 128);   // (8, 64)
    gemm_cp_kernel<2><<<ggrid, 256, SMEM_G2>>>(cq, cWq, gQ);  // Q: tf32 + scale
    gemm_cp_kernel<1><<<ggrid, 256, SMEM_G2>>>(ck, cWk, gK);  // K: tf32
    gemm_cp_kernel<1><<<ggrid, 256, SMEM_G2>>>(cv, cWv, gV);  // V: tf32

    dim3 agrid(BATCH * HH, SEQ / QTILE);   // (64, 16)
    attn_mma4_kernel<<<agrid, 128, attn_smem>>>(gQ, gK, gV, gC);

    gemm_cp_kernel<0><<<ggrid, 256, SMEM_G2>>>(gC, cWo, out); // plain f32 out
}